// round 6
// baseline (speedup 1.0000x reference)
#include <cuda_runtime.h>
#include <cstdint>

// ---------------------------------------------------------------------------
// FAENet forward. N=50000 nodes, E=800000 edges, H=256, F=128, G=50, L=3.
// Heavy GEMMs use split-TF32 mma.sync (fp32-class accuracy, tensor-core rate).
// ---------------------------------------------------------------------------

#define MAX_N 50000
#define MAX_E 800000

__device__ float g_h0 [MAX_N * 256];
__device__ float g_hb [MAX_N * 256];
__device__ float g_h  [MAX_N * 256];
__device__ float g_hd [MAX_N * 128];
__device__ float g_agg[MAX_N * 128];
__device__ float g_stats[512];
__device__ float g_t  [MAX_E * 128];
__device__ float g_e  [MAX_E * 128];

__device__ __forceinline__ float silu_f(float x) {
    return x / (1.0f + __expf(-x));
}

__device__ __forceinline__ float tf32_rna(float x) {
    float r;
    asm("cvt.rna.tf32.f32 %0, %1;" : "=f"(r) : "f"(x));
    return r;
}

__device__ __forceinline__ void mma8(float* d, const uint32_t* a, uint32_t b0, uint32_t b1) {
    asm volatile(
        "mma.sync.aligned.m16n8k8.row.col.f32.tf32.tf32.f32 "
        "{%0,%1,%2,%3}, {%4,%5,%6,%7}, {%8,%9}, {%0,%1,%2,%3};"
        : "+f"(d[0]), "+f"(d[1]), "+f"(d[2]), "+f"(d[3])
        : "r"(a[0]), "r"(a[1]), "r"(a[2]), "r"(a[3]), "r"(b0), "r"(b1));
}

__device__ __forceinline__ void red2(float* p, float a, float b) {
    asm volatile("red.global.add.v2.f32 [%0], {%1,%2};"
                 :: "l"(p), "f"(a), "f"(b) : "memory");
}

#define LDP 132   // smem leading dim pad: bank = (4c + r) % 32, conflict-free

// ---------------------------------------------------------------------------
// Split-TF32 GEMM: C = (res?) + silu(A @ W^T + bias). W [Nout,K] row-major.
// BM=BN=128, BK=16, 256 threads, warp tile 32x64. K%16==0, Nout%128==0.
// ---------------------------------------------------------------------------
__global__ void __launch_bounds__(256) gemm_tc(
    const float* __restrict__ A, const float* __restrict__ W,
    const float* __restrict__ bias, float* __restrict__ C,
    const float* __restrict__ res, int M, int N, int K)
{
    __shared__ float Ah[16][LDP], Al[16][LDP], Bh[16][LDP], Bl[16][LDP];

    const int tid  = threadIdx.x;
    const int br   = blockIdx.x * 128;
    const int bc   = blockIdx.y * 128;
    const int wid  = tid >> 5;
    const int wm   = wid & 3;          // 4 warps along M (32 rows each)
    const int wn   = wid >> 2;         // 2 warps along N (64 cols each)
    const int lane = tid & 31;
    const int r    = lane >> 2;
    const int c    = lane & 3;
    const int lr   = tid & 127;
    const int kq   = (tid >> 7) * 8;

    float acc[2][8][4];
#pragma unroll
    for (int mi = 0; mi < 2; mi++)
#pragma unroll
        for (int ni = 0; ni < 8; ni++)
#pragma unroll
            for (int v = 0; v < 4; v++) acc[mi][ni][v] = 0.f;

    const int  arow = br + lr;
    const bool a_ok = arow < M;
    const float* Ap = A + (size_t)arow * K + kq;
    const float* Wp = W + (size_t)(bc + lr) * K + kq;

    float4 av0, av1, wv0, wv1;
    av0 = a_ok ? *(const float4*)(Ap)     : make_float4(0.f,0.f,0.f,0.f);
    av1 = a_ok ? *(const float4*)(Ap + 4) : make_float4(0.f,0.f,0.f,0.f);
    wv0 = *(const float4*)(Wp);
    wv1 = *(const float4*)(Wp + 4);

    for (int k0 = 0; k0 < K; k0 += 16) {
        // split-store staged regs
        {
            float a8[8] = {av0.x,av0.y,av0.z,av0.w,av1.x,av1.y,av1.z,av1.w};
            float w8[8] = {wv0.x,wv0.y,wv0.z,wv0.w,wv1.x,wv1.y,wv1.z,wv1.w};
#pragma unroll
            for (int q = 0; q < 8; q++) {
                float hi = tf32_rna(a8[q]);
                Ah[kq + q][lr] = hi;
                Al[kq + q][lr] = tf32_rna(a8[q] - hi);
                float whi = tf32_rna(w8[q]);
                Bh[kq + q][lr] = whi;
                Bl[kq + q][lr] = tf32_rna(w8[q] - whi);
            }
        }
        __syncthreads();
        if (k0 + 16 < K) {
            av0 = a_ok ? *(const float4*)(Ap + k0 + 16) : make_float4(0.f,0.f,0.f,0.f);
            av1 = a_ok ? *(const float4*)(Ap + k0 + 20) : make_float4(0.f,0.f,0.f,0.f);
            wv0 = *(const float4*)(Wp + k0 + 16);
            wv1 = *(const float4*)(Wp + k0 + 20);
        }
#pragma unroll
        for (int ks = 0; ks < 16; ks += 8) {
            uint32_t ah[2][4], al[2][4];
#pragma unroll
            for (int mi = 0; mi < 2; mi++) {
                int row0 = wm * 32 + mi * 16 + r;
                ah[mi][0] = __float_as_uint(Ah[ks + c    ][row0]);
                ah[mi][1] = __float_as_uint(Ah[ks + c    ][row0 + 8]);
                ah[mi][2] = __float_as_uint(Ah[ks + c + 4][row0]);
                ah[mi][3] = __float_as_uint(Ah[ks + c + 4][row0 + 8]);
                al[mi][0] = __float_as_uint(Al[ks + c    ][row0]);
                al[mi][1] = __float_as_uint(Al[ks + c    ][row0 + 8]);
                al[mi][2] = __float_as_uint(Al[ks + c + 4][row0]);
                al[mi][3] = __float_as_uint(Al[ks + c + 4][row0 + 8]);
            }
#pragma unroll
            for (int ni = 0; ni < 8; ni++) {
                int col = wn * 64 + ni * 8 + r;
                uint32_t bh0 = __float_as_uint(Bh[ks + c    ][col]);
                uint32_t bh1 = __float_as_uint(Bh[ks + c + 4][col]);
                uint32_t bl0 = __float_as_uint(Bl[ks + c    ][col]);
                uint32_t bl1 = __float_as_uint(Bl[ks + c + 4][col]);
#pragma unroll
                for (int mi = 0; mi < 2; mi++) {
                    mma8(acc[mi][ni], ah[mi], bh0, bh1);
                    mma8(acc[mi][ni], ah[mi], bl0, bl1);
                    mma8(acc[mi][ni], al[mi], bh0, bh1);
                }
            }
        }
        __syncthreads();
    }

#pragma unroll
    for (int ni = 0; ni < 8; ni++) {
        int gcol = bc + wn * 64 + ni * 8 + 2 * c;
        float b0 = bias[gcol], b1 = bias[gcol + 1];
#pragma unroll
        for (int mi = 0; mi < 2; mi++) {
            int grow = br + wm * 32 + mi * 16 + r;
#pragma unroll
            for (int half = 0; half < 2; half++) {
                int gr = grow + half * 8;
                if (gr < M) {
                    float v0 = silu_f(acc[mi][ni][half * 2 + 0] + b0);
                    float v1 = silu_f(acc[mi][ni][half * 2 + 1] + b1);
                    float* cp = C + (size_t)gr * N + gcol;
                    if (res) {
                        const float2 rv = *(const float2*)(res + (size_t)gr * N + gcol);
                        v0 += rv.x; v1 += rv.y;
                    }
                    *(float2*)cp = make_float2(v0, v1);
                }
            }
        }
    }
}

// ---------------------------------------------------------------------------
// Message kernel: e_l = silu(e @ gw^T + gb); msg = e_l * hd[src];
// red.v2 into agg[dst]. Same split-TF32 mainloop, 128 edges/block, K=N=128.
// ---------------------------------------------------------------------------
__global__ void __launch_bounds__(256) message_tc(
    const float* __restrict__ e, const float* __restrict__ gw,
    const float* __restrict__ gb, const float* __restrict__ hd,
    const int* __restrict__ ei, float* __restrict__ agg, int E)
{
    __shared__ float Ah[16][LDP], Al[16][LDP], Bh[16][LDP], Bl[16][LDP];
    __shared__ int s_src[128];
    __shared__ int s_dst[128];

    const int tid  = threadIdx.x;
    const int br   = blockIdx.x * 128;
    const int wid  = tid >> 5;
    const int wm   = wid & 3;
    const int wn   = wid >> 2;
    const int lane = tid & 31;
    const int r    = lane >> 2;
    const int c    = lane & 3;
    const int lr   = tid & 127;
    const int kq   = (tid >> 7) * 8;

    if (tid < 128) {
        int ge = br + tid;
        s_src[tid] = (ge < E) ? ei[ge]     : 0;
        s_dst[tid] = (ge < E) ? ei[E + ge] : 0;
    }

    float acc[2][8][4];
#pragma unroll
    for (int mi = 0; mi < 2; mi++)
#pragma unroll
        for (int ni = 0; ni < 8; ni++)
#pragma unroll
            for (int v = 0; v < 4; v++) acc[mi][ni][v] = 0.f;

    const int  arow = br + lr;
    const bool a_ok = arow < E;
    const float* Ap = e  + (size_t)arow * 128 + kq;
    const float* Wp = gw + (size_t)lr   * 128 + kq;

    float4 av0, av1, wv0, wv1;
    av0 = a_ok ? *(const float4*)(Ap)     : make_float4(0.f,0.f,0.f,0.f);
    av1 = a_ok ? *(const float4*)(Ap + 4) : make_float4(0.f,0.f,0.f,0.f);
    wv0 = *(const float4*)(Wp);
    wv1 = *(const float4*)(Wp + 4);

    for (int k0 = 0; k0 < 128; k0 += 16) {
        {
            float a8[8] = {av0.x,av0.y,av0.z,av0.w,av1.x,av1.y,av1.z,av1.w};
            float w8[8] = {wv0.x,wv0.y,wv0.z,wv0.w,wv1.x,wv1.y,wv1.z,wv1.w};
#pragma unroll
            for (int q = 0; q < 8; q++) {
                float hi = tf32_rna(a8[q]);
                Ah[kq + q][lr] = hi;
                Al[kq + q][lr] = tf32_rna(a8[q] - hi);
                float whi = tf32_rna(w8[q]);
                Bh[kq + q][lr] = whi;
                Bl[kq + q][lr] = tf32_rna(w8[q] - whi);
            }
        }
        __syncthreads();
        if (k0 + 16 < 128) {
            av0 = a_ok ? *(const float4*)(Ap + k0 + 16) : make_float4(0.f,0.f,0.f,0.f);
            av1 = a_ok ? *(const float4*)(Ap + k0 + 20) : make_float4(0.f,0.f,0.f,0.f);
            wv0 = *(const float4*)(Wp + k0 + 16);
            wv1 = *(const float4*)(Wp + k0 + 20);
        }
#pragma unroll
        for (int ks = 0; ks < 16; ks += 8) {
            uint32_t ah[2][4], al[2][4];
#pragma unroll
            for (int mi = 0; mi < 2; mi++) {
                int row0 = wm * 32 + mi * 16 + r;
                ah[mi][0] = __float_as_uint(Ah[ks + c    ][row0]);
                ah[mi][1] = __float_as_uint(Ah[ks + c    ][row0 + 8]);
                ah[mi][2] = __float_as_uint(Ah[ks + c + 4][row0]);
                ah[mi][3] = __float_as_uint(Ah[ks + c + 4][row0 + 8]);
                al[mi][0] = __float_as_uint(Al[ks + c    ][row0]);
                al[mi][1] = __float_as_uint(Al[ks + c    ][row0 + 8]);
                al[mi][2] = __float_as_uint(Al[ks + c + 4][row0]);
                al[mi][3] = __float_as_uint(Al[ks + c + 4][row0 + 8]);
            }
#pragma unroll
            for (int ni = 0; ni < 8; ni++) {
                int col = wn * 64 + ni * 8 + r;
                uint32_t bh0 = __float_as_uint(Bh[ks + c    ][col]);
                uint32_t bh1 = __float_as_uint(Bh[ks + c + 4][col]);
                uint32_t bl0 = __float_as_uint(Bl[ks + c    ][col]);
                uint32_t bl1 = __float_as_uint(Bl[ks + c + 4][col]);
#pragma unroll
                for (int mi = 0; mi < 2; mi++) {
                    mma8(acc[mi][ni], ah[mi], bh0, bh1);
                    mma8(acc[mi][ni], ah[mi], bl0, bl1);
                    mma8(acc[mi][ni], al[mi], bh0, bh1);
                }
            }
        }
        __syncthreads();
    }

    // epilogue: silu + gather hd[src] + red into agg[dst]
#pragma unroll
    for (int mi = 0; mi < 2; mi++) {
#pragma unroll
        for (int half = 0; half < 2; half++) {
            int lrow = wm * 32 + mi * 16 + r + half * 8;
            int ge   = br + lrow;
            if (ge < E) {
                int s = s_src[lrow];
                int d = s_dst[lrow];
                const float* hp = hd  + (size_t)s * 128;
                float*       ap = agg + (size_t)d * 128;
#pragma unroll
                for (int ni = 0; ni < 8; ni++) {
                    int colb = wn * 64 + ni * 8 + 2 * c;
                    float2 hv = *(const float2*)(hp + colb);
                    float m0 = silu_f(acc[mi][ni][half * 2 + 0] + gb[colb])     * hv.x;
                    float m1 = silu_f(acc[mi][ni][half * 2 + 1] + gb[colb + 1]) * hv.y;
                    red2(ap + colb, m0, m1);
                }
            }
        }
    }
}

// ---------------------------------------------------------------------------
// Edge stage 1 (unchanged this round): t = silu([rel_pos|edge_attr]@[W1|W12]^T + b)
// ---------------------------------------------------------------------------
__global__ void __launch_bounds__(256, 2) edge_stage1(
    const float* __restrict__ rel_pos, const float* __restrict__ edge_attr,
    const float* __restrict__ w1, const float* __restrict__ b1,
    const float* __restrict__ w12, const float* __restrict__ b12,
    float* __restrict__ t, int E)
{
    __shared__ float As[8][128];
    __shared__ float Bs[8][128];

    const int tid = threadIdx.x;
    const int br  = blockIdx.x * 128;
    const int tr  = (tid >> 4) * 8;
    const int tc  = (tid & 15) * 8;
    const int lr  = tid & 127;
    const int kq  = (tid >> 7) * 4;

    float acc[8][8];
#pragma unroll
    for (int i = 0; i < 8; i++)
#pragma unroll
        for (int j = 0; j < 8; j++) acc[i][j] = 0.f;

    const int  ge   = br + lr;
    const bool e_ok = ge < E;

    for (int k0 = 0; k0 < 56; k0 += 8) {
#pragma unroll
        for (int q = 0; q < 4; q++) {
            int k = k0 + kq + q;
            float av = 0.f, wv = 0.f;
            if (e_ok) {
                if (k < 3)       av = rel_pos[(size_t)ge * 3 + k];
                else if (k < 53) av = edge_attr[(size_t)ge * 50 + (k - 3)];
            }
            if (lr < 64) {
                if (k < 3)       wv = w1[lr * 3 + k];
            } else {
                if (k >= 3 && k < 53) wv = w12[(lr - 64) * 50 + (k - 3)];
            }
            As[kq + q][lr] = av;
            Bs[kq + q][lr] = wv;
        }
        __syncthreads();
#pragma unroll
        for (int k = 0; k < 8; k++) {
            float4 a0 = *(const float4*)&As[k][tr];
            float4 a1 = *(const float4*)&As[k][tr + 4];
            float4 b0 = *(const float4*)&Bs[k][tc];
            float4 b1 = *(const float4*)&Bs[k][tc + 4];
            float a[8] = {a0.x, a0.y, a0.z, a0.w, a1.x, a1.y, a1.z, a1.w};
            float b[8] = {b0.x, b0.y, b0.z, b0.w, b1.x, b1.y, b1.z, b1.w};
#pragma unroll
            for (int i = 0; i < 8; i++)
#pragma unroll
                for (int j = 0; j < 8; j++)
                    acc[i][j] = fmaf(a[i], b[j], acc[i][j]);
        }
        __syncthreads();
    }

    float bb[8];
#pragma unroll
    for (int j = 0; j < 8; j++) {
        int cc = tc + j;
        bb[j] = (cc < 64) ? b1[cc] : b12[cc - 64];
    }

#pragma unroll
    for (int i = 0; i < 8; i++) {
        int g = br + tr + i;
        if (g < E) {
            float* row = t + (size_t)g * 128 + tc;
            float v[8];
#pragma unroll
            for (int j = 0; j < 8; j++) v[j] = silu_f(acc[i][j] + bb[j]);
            *(float4*)row       = make_float4(v[0], v[1], v[2], v[3]);
            *(float4*)(row + 4) = make_float4(v[4], v[5], v[6], v[7]);
        }
    }
}

// ---------------------------------------------------------------------------
__global__ void embed_concat(const int* __restrict__ z, const int* __restrict__ tag,
                             const float* __restrict__ emb_w,
                             const float* __restrict__ tag_emb_w,
                             float* __restrict__ h0, int N)
{
    int idx = blockIdx.x * blockDim.x + threadIdx.x;
    if (idx >= N * 64) return;
    int n = idx >> 6, c4 = idx & 63;
    float4 v;
    if (c4 < 56) v = ((const float4*)(emb_w + (size_t)z[n] * 224))[c4];
    else         v = ((const float4*)(tag_emb_w + (size_t)tag[n] * 32))[c4 - 56];
    ((float4*)(h0 + (size_t)n * 256))[c4] = v;
}

__global__ void stats_kernel(const float* __restrict__ agg, float* __restrict__ stats, int N)
{
    int col = threadIdx.x;
    float s = 0.f, s2 = 0.f;
    for (int r = blockIdx.x; r < N; r += gridDim.x) {
        float v = agg[(size_t)r * 128 + col];
        s += v;
        s2 = fmaf(v, v, s2);
    }
    atomicAdd(&stats[col], s);
    atomicAdd(&stats[128 + col], s2);
}

__global__ void finalize_stats(float* stats, const float* __restrict__ gnw,
                               const float* __restrict__ gnms, int N)
{
    int f = threadIdx.x;
    float inv  = 1.f / (float)N;
    float mean = stats[f] * inv;
    float m2   = stats[128 + f] * inv;
    float ms   = gnms[f];
    float var = m2 - ms * (2.f - ms) * mean * mean;
    stats[256 + f] = mean * ms;
    stats[384 + f] = gnw[f] * rsqrtf(var + 1e-5f);
}

__global__ void apply_gn(const float* __restrict__ agg, const float* __restrict__ stats,
                         const float* __restrict__ gnb, float* __restrict__ x, int total4)
{
    int i = blockIdx.x * blockDim.x + threadIdx.x;
    if (i >= total4) return;
    int f = (i & 31) * 4;
    float4 v = ((const float4*)agg)[i];
    float4 o;
    o.x = silu_f(stats[384 + f + 0] * (v.x - stats[256 + f + 0]) + gnb[f + 0]);
    o.y = silu_f(stats[384 + f + 1] * (v.y - stats[256 + f + 1]) + gnb[f + 1]);
    o.z = silu_f(stats[384 + f + 2] * (v.z - stats[256 + f + 2]) + gnb[f + 2]);
    o.w = silu_f(stats[384 + f + 3] * (v.w - stats[256 + f + 3]) + gnb[f + 3]);
    ((float4*)x)[i] = o;
}

__global__ void out_reduce(const float* __restrict__ h1, const float* __restrict__ w2,
                           const float* __restrict__ b2, const int* __restrict__ batch,
                           float* __restrict__ out, int N)
{
    int gw   = (blockIdx.x * blockDim.x + threadIdx.x) >> 5;
    int lane = threadIdx.x & 31;
    if (gw >= N) return;
    float4 a = ((const float4*)(h1 + (size_t)gw * 128))[lane];
    float4 b = ((const float4*)w2)[lane];
    float s = a.x * b.x + a.y * b.y + a.z * b.z + a.w * b.w;
#pragma unroll
    for (int o = 16; o > 0; o >>= 1) s += __shfl_xor_sync(0xffffffffu, s, o);
    if (lane == 0) atomicAdd(&out[batch[gw]], s + b2[0]);
}

__global__ void zero_kernel(float* __restrict__ p, int n4)
{
    int i = blockIdx.x * blockDim.x + threadIdx.x;
    if (i < n4) ((float4*)p)[i] = make_float4(0.f, 0.f, 0.f, 0.f);
}

// ---------------------------------------------------------------------------
extern "C" void kernel_launch(void* const* d_in, const int* in_sizes, int n_in,
                              void* d_out, int out_size)
{
    const int*   z         = (const int*)  d_in[0];
    const int*   tag       = (const int*)  d_in[1];
    const float* rel_pos   = (const float*)d_in[2];
    const float* edge_attr = (const float*)d_in[3];
    const int*   ei        = (const int*)  d_in[4];
    const int*   batch     = (const int*)  d_in[5];
    const float* lin_e1_w  = (const float*)d_in[6];
    const float* lin_e1_b  = (const float*)d_in[7];
    const float* lin_e12_w = (const float*)d_in[8];
    const float* lin_e12_b = (const float*)d_in[9];
    const float* lin_e2_w  = (const float*)d_in[10];
    const float* lin_e2_b  = (const float*)d_in[11];
    const float* emb_w     = (const float*)d_in[12];
    const float* tag_emb_w = (const float*)d_in[13];
    const float* lin_w     = (const float*)d_in[14];
    const float* lin_b     = (const float*)d_in[15];
    const float* lin2_w    = (const float*)d_in[16];
    const float* lin2_b    = (const float*)d_in[17];
    const float* geom_w    = (const float*)d_in[18];
    const float* geom_b    = (const float*)d_in[19];
    const float* down_w    = (const float*)d_in[20];
    const float* down_b    = (const float*)d_in[21];
    const float* up_w      = (const float*)d_in[22];
    const float* up_b      = (const float*)d_in[23];
    const float* gn_w      = (const float*)d_in[24];
    const float* gn_b      = (const float*)d_in[25];
    const float* gn_ms     = (const float*)d_in[26];
    const float* out1_w    = (const float*)d_in[27];
    const float* out1_b    = (const float*)d_in[28];
    const float* out2_w    = (const float*)d_in[29];
    const float* out2_b    = (const float*)d_in[30];
    float*       out       = (float*)d_out;

    const int N = in_sizes[0];
    const int E = in_sizes[2] / 3;

    float *h0, *hb, *h, *hd, *agg, *stats, *t, *e;
    cudaGetSymbolAddress((void**)&h0,    g_h0);
    cudaGetSymbolAddress((void**)&hb,    g_hb);
    cudaGetSymbolAddress((void**)&h,     g_h);
    cudaGetSymbolAddress((void**)&hd,    g_hd);
    cudaGetSymbolAddress((void**)&agg,   g_agg);
    cudaGetSymbolAddress((void**)&stats, g_stats);
    cudaGetSymbolAddress((void**)&t,     g_t);
    cudaGetSymbolAddress((void**)&e,     g_e);

    const int mbn = (N + 127) / 128;
    const int mbe = (E + 127) / 128;

    // Node embedding
    embed_concat<<<(N * 64 + 255) / 256, 256>>>(z, tag, emb_w, tag_emb_w, h0, N);
    gemm_tc<<<dim3(mbn, 2), 256>>>(h0, lin_w,  lin_b,  hb, nullptr, N, 256, 256);
    gemm_tc<<<dim3(mbn, 2), 256>>>(hb, lin2_w, lin2_b, h,  nullptr, N, 256, 256);

    // Edge embedding
    edge_stage1<<<mbe, 256>>>(rel_pos, edge_attr, lin_e1_w, lin_e1_b,
                              lin_e12_w, lin_e12_b, t, E);
    gemm_tc<<<dim3(mbe, 1), 256>>>(t, lin_e2_w, lin_e2_b, e, nullptr, E, 128, 128);

    // Interaction layers
    for (int l = 0; l < 3; l++) {
        gemm_tc<<<dim3(mbn, 1), 256>>>(h, down_w + (size_t)l * 128 * 256,
                                       down_b + l * 128, hd, nullptr, N, 128, 256);
        zero_kernel<<<(N * 32 + 255) / 256, 256>>>(agg, N * 32);
        zero_kernel<<<1, 64>>>(stats, 64);
        message_tc<<<mbe, 256>>>(e, geom_w + (size_t)l * 128 * 128,
                                 geom_b + l * 128, hd, ei, agg, E);
        stats_kernel<<<256, 128>>>(agg, stats, N);
        finalize_stats<<<1, 128>>>(stats, gn_w + l * 128, gn_ms + l * 128, N);
        apply_gn<<<(N * 32 + 255) / 256, 256>>>(agg, stats, gn_b + l * 128, hd, N * 32);
        gemm_tc<<<dim3(mbn, 2), 256>>>(hd, up_w + (size_t)l * 256 * 128,
                                       up_b + l * 256, h, h, N, 256, 128);
    }

    // Output block
    gemm_tc<<<dim3(mbn, 1), 256>>>(h, out1_w, out1_b, hd, nullptr, N, 128, 256);
    zero_kernel<<<1, 8>>>(out, 8);
    out_reduce<<<(N * 32 + 255) / 256, 256>>>(hd, out2_w, out2_b, batch, out, N);
}

// round 7
// speedup vs baseline: 1.0032x; 1.0032x over previous
#include <cuda_runtime.h>
#include <cstdint>

// ---------------------------------------------------------------------------
// FAENet forward. N=50000 nodes, E=800000 edges, H=256, F=128, G=50, L=3.
// Heavy GEMMs use split-TF32 mma.sync (fp32-class accuracy, tensor-core rate).
// ---------------------------------------------------------------------------

#define MAX_N 50000
#define MAX_E 800000

__device__ float g_h0 [MAX_N * 256];
__device__ float g_hb [MAX_N * 256];
__device__ float g_h  [MAX_N * 256];
__device__ float g_hd [MAX_N * 128];
__device__ float g_agg[MAX_N * 128];
__device__ float g_stats[512];
__device__ float g_t  [MAX_E * 128];
__device__ float g_e  [MAX_E * 128];

__device__ __forceinline__ float silu_f(float x) {
    return x / (1.0f + __expf(-x));
}

__device__ __forceinline__ float tf32_rna(float x) {
    float r;
    asm("cvt.rna.tf32.f32 %0, %1;" : "=f"(r) : "f"(x));
    return r;
}

__device__ __forceinline__ void mma8(float* d, const uint32_t* a, uint32_t b0, uint32_t b1) {
    asm volatile(
        "mma.sync.aligned.m16n8k8.row.col.f32.tf32.tf32.f32 "
        "{%0,%1,%2,%3}, {%4,%5,%6,%7}, {%8,%9}, {%0,%1,%2,%3};"
        : "+f"(d[0]), "+f"(d[1]), "+f"(d[2]), "+f"(d[3])
        : "r"(a[0]), "r"(a[1]), "r"(a[2]), "r"(a[3]), "r"(b0), "r"(b1));
}

__device__ __forceinline__ void red2(float* p, float a, float b) {
    asm volatile("red.global.add.v2.f32 [%0], {%1,%2};"
                 :: "l"(p), "f"(a), "f"(b) : "memory");
}

#define LDP 132   // smem leading dim pad: bank = (4c + r) % 32, conflict-free

// ---------------------------------------------------------------------------
// Split-TF32 GEMM: C = (res?) + silu(A @ W^T + bias). W [Nout,K] row-major.
// BM=BN=128, BK=16, 256 threads, warp tile 32x64. K%16==0, Nout%128==0.
// ---------------------------------------------------------------------------
__global__ void __launch_bounds__(256) gemm_tc(
    const float* __restrict__ A, const float* __restrict__ W,
    const float* __restrict__ bias, float* __restrict__ C,
    const float* __restrict__ res, int M, int N, int K)
{
    __shared__ float Ah[16][LDP], Al[16][LDP], Bh[16][LDP], Bl[16][LDP];

    const int tid  = threadIdx.x;
    const int br   = blockIdx.x * 128;
    const int bc   = blockIdx.y * 128;
    const int wid  = tid >> 5;
    const int wm   = wid & 3;          // 4 warps along M (32 rows each)
    const int wn   = wid >> 2;         // 2 warps along N (64 cols each)
    const int lane = tid & 31;
    const int r    = lane >> 2;
    const int c    = lane & 3;
    const int lr   = tid & 127;
    const int kq   = (tid >> 7) * 8;

    float acc[2][8][4];
#pragma unroll
    for (int mi = 0; mi < 2; mi++)
#pragma unroll
        for (int ni = 0; ni < 8; ni++)
#pragma unroll
            for (int v = 0; v < 4; v++) acc[mi][ni][v] = 0.f;

    const int  arow = br + lr;
    const bool a_ok = arow < M;
    const float* Ap = A + (size_t)arow * K + kq;
    const float* Wp = W + (size_t)(bc + lr) * K + kq;

    float4 av0, av1, wv0, wv1;
    av0 = a_ok ? *(const float4*)(Ap)     : make_float4(0.f,0.f,0.f,0.f);
    av1 = a_ok ? *(const float4*)(Ap + 4) : make_float4(0.f,0.f,0.f,0.f);
    wv0 = *(const float4*)(Wp);
    wv1 = *(const float4*)(Wp + 4);

    for (int k0 = 0; k0 < K; k0 += 16) {
        // split-store staged regs
        {
            float a8[8] = {av0.x,av0.y,av0.z,av0.w,av1.x,av1.y,av1.z,av1.w};
            float w8[8] = {wv0.x,wv0.y,wv0.z,wv0.w,wv1.x,wv1.y,wv1.z,wv1.w};
#pragma unroll
            for (int q = 0; q < 8; q++) {
                float hi = tf32_rna(a8[q]);
                Ah[kq + q][lr] = hi;
                Al[kq + q][lr] = tf32_rna(a8[q] - hi);
                float whi = tf32_rna(w8[q]);
                Bh[kq + q][lr] = whi;
                Bl[kq + q][lr] = tf32_rna(w8[q] - whi);
            }
        }
        __syncthreads();
        if (k0 + 16 < K) {
            av0 = a_ok ? *(const float4*)(Ap + k0 + 16) : make_float4(0.f,0.f,0.f,0.f);
            av1 = a_ok ? *(const float4*)(Ap + k0 + 20) : make_float4(0.f,0.f,0.f,0.f);
            wv0 = *(const float4*)(Wp + k0 + 16);
            wv1 = *(const float4*)(Wp + k0 + 20);
        }
#pragma unroll
        for (int ks = 0; ks < 16; ks += 8) {
            uint32_t ah[2][4], al[2][4];
#pragma unroll
            for (int mi = 0; mi < 2; mi++) {
                int row0 = wm * 32 + mi * 16 + r;
                ah[mi][0] = __float_as_uint(Ah[ks + c    ][row0]);
                ah[mi][1] = __float_as_uint(Ah[ks + c    ][row0 + 8]);
                ah[mi][2] = __float_as_uint(Ah[ks + c + 4][row0]);
                ah[mi][3] = __float_as_uint(Ah[ks + c + 4][row0 + 8]);
                al[mi][0] = __float_as_uint(Al[ks + c    ][row0]);
                al[mi][1] = __float_as_uint(Al[ks + c    ][row0 + 8]);
                al[mi][2] = __float_as_uint(Al[ks + c + 4][row0]);
                al[mi][3] = __float_as_uint(Al[ks + c + 4][row0 + 8]);
            }
#pragma unroll
            for (int ni = 0; ni < 8; ni++) {
                int col = wn * 64 + ni * 8 + r;
                uint32_t bh0 = __float_as_uint(Bh[ks + c    ][col]);
                uint32_t bh1 = __float_as_uint(Bh[ks + c + 4][col]);
                uint32_t bl0 = __float_as_uint(Bl[ks + c    ][col]);
                uint32_t bl1 = __float_as_uint(Bl[ks + c + 4][col]);
#pragma unroll
                for (int mi = 0; mi < 2; mi++) {
                    mma8(acc[mi][ni], ah[mi], bh0, bh1);
                    mma8(acc[mi][ni], ah[mi], bl0, bl1);
                    mma8(acc[mi][ni], al[mi], bh0, bh1);
                }
            }
        }
        __syncthreads();
    }

#pragma unroll
    for (int ni = 0; ni < 8; ni++) {
        int gcol = bc + wn * 64 + ni * 8 + 2 * c;
        float b0 = bias[gcol], b1 = bias[gcol + 1];
#pragma unroll
        for (int mi = 0; mi < 2; mi++) {
            int grow = br + wm * 32 + mi * 16 + r;
#pragma unroll
            for (int half = 0; half < 2; half++) {
                int gr = grow + half * 8;
                if (gr < M) {
                    float v0 = silu_f(acc[mi][ni][half * 2 + 0] + b0);
                    float v1 = silu_f(acc[mi][ni][half * 2 + 1] + b1);
                    float* cp = C + (size_t)gr * N + gcol;
                    if (res) {
                        const float2 rv = *(const float2*)(res + (size_t)gr * N + gcol);
                        v0 += rv.x; v1 += rv.y;
                    }
                    *(float2*)cp = make_float2(v0, v1);
                }
            }
        }
    }
}

// ---------------------------------------------------------------------------
// Message kernel: e_l = silu(e @ gw^T + gb); msg = e_l * hd[src];
// red.v2 into agg[dst]. Same split-TF32 mainloop, 128 edges/block, K=N=128.
// ---------------------------------------------------------------------------
__global__ void __launch_bounds__(256) message_tc(
    const float* __restrict__ e, const float* __restrict__ gw,
    const float* __restrict__ gb, const float* __restrict__ hd,
    const int* __restrict__ ei, float* __restrict__ agg, int E)
{
    __shared__ float Ah[16][LDP], Al[16][LDP], Bh[16][LDP], Bl[16][LDP];
    __shared__ int s_src[128];
    __shared__ int s_dst[128];

    const int tid  = threadIdx.x;
    const int br   = blockIdx.x * 128;
    const int wid  = tid >> 5;
    const int wm   = wid & 3;
    const int wn   = wid >> 2;
    const int lane = tid & 31;
    const int r    = lane >> 2;
    const int c    = lane & 3;
    const int lr   = tid & 127;
    const int kq   = (tid >> 7) * 8;

    if (tid < 128) {
        int ge = br + tid;
        s_src[tid] = (ge < E) ? ei[ge]     : 0;
        s_dst[tid] = (ge < E) ? ei[E + ge] : 0;
    }

    float acc[2][8][4];
#pragma unroll
    for (int mi = 0; mi < 2; mi++)
#pragma unroll
        for (int ni = 0; ni < 8; ni++)
#pragma unroll
            for (int v = 0; v < 4; v++) acc[mi][ni][v] = 0.f;

    const int  arow = br + lr;
    const bool a_ok = arow < E;
    const float* Ap = e  + (size_t)arow * 128 + kq;
    const float* Wp = gw + (size_t)lr   * 128 + kq;

    float4 av0, av1, wv0, wv1;
    av0 = a_ok ? *(const float4*)(Ap)     : make_float4(0.f,0.f,0.f,0.f);
    av1 = a_ok ? *(const float4*)(Ap + 4) : make_float4(0.f,0.f,0.f,0.f);
    wv0 = *(const float4*)(Wp);
    wv1 = *(const float4*)(Wp + 4);

    for (int k0 = 0; k0 < 128; k0 += 16) {
        {
            float a8[8] = {av0.x,av0.y,av0.z,av0.w,av1.x,av1.y,av1.z,av1.w};
            float w8[8] = {wv0.x,wv0.y,wv0.z,wv0.w,wv1.x,wv1.y,wv1.z,wv1.w};
#pragma unroll
            for (int q = 0; q < 8; q++) {
                float hi = tf32_rna(a8[q]);
                Ah[kq + q][lr] = hi;
                Al[kq + q][lr] = tf32_rna(a8[q] - hi);
                float whi = tf32_rna(w8[q]);
                Bh[kq + q][lr] = whi;
                Bl[kq + q][lr] = tf32_rna(w8[q] - whi);
            }
        }
        __syncthreads();
        if (k0 + 16 < 128) {
            av0 = a_ok ? *(const float4*)(Ap + k0 + 16) : make_float4(0.f,0.f,0.f,0.f);
            av1 = a_ok ? *(const float4*)(Ap + k0 + 20) : make_float4(0.f,0.f,0.f,0.f);
            wv0 = *(const float4*)(Wp + k0 + 16);
            wv1 = *(const float4*)(Wp + k0 + 20);
        }
#pragma unroll
        for (int ks = 0; ks < 16; ks += 8) {
            uint32_t ah[2][4], al[2][4];
#pragma unroll
            for (int mi = 0; mi < 2; mi++) {
                int row0 = wm * 32 + mi * 16 + r;
                ah[mi][0] = __float_as_uint(Ah[ks + c    ][row0]);
                ah[mi][1] = __float_as_uint(Ah[ks + c    ][row0 + 8]);
                ah[mi][2] = __float_as_uint(Ah[ks + c + 4][row0]);
                ah[mi][3] = __float_as_uint(Ah[ks + c + 4][row0 + 8]);
                al[mi][0] = __float_as_uint(Al[ks + c    ][row0]);
                al[mi][1] = __float_as_uint(Al[ks + c    ][row0 + 8]);
                al[mi][2] = __float_as_uint(Al[ks + c + 4][row0]);
                al[mi][3] = __float_as_uint(Al[ks + c + 4][row0 + 8]);
            }
#pragma unroll
            for (int ni = 0; ni < 8; ni++) {
                int col = wn * 64 + ni * 8 + r;
                uint32_t bh0 = __float_as_uint(Bh[ks + c    ][col]);
                uint32_t bh1 = __float_as_uint(Bh[ks + c + 4][col]);
                uint32_t bl0 = __float_as_uint(Bl[ks + c    ][col]);
                uint32_t bl1 = __float_as_uint(Bl[ks + c + 4][col]);
#pragma unroll
                for (int mi = 0; mi < 2; mi++) {
                    mma8(acc[mi][ni], ah[mi], bh0, bh1);
                    mma8(acc[mi][ni], ah[mi], bl0, bl1);
                    mma8(acc[mi][ni], al[mi], bh0, bh1);
                }
            }
        }
        __syncthreads();
    }

    // epilogue: silu + gather hd[src] + red into agg[dst]
#pragma unroll
    for (int mi = 0; mi < 2; mi++) {
#pragma unroll
        for (int half = 0; half < 2; half++) {
            int lrow = wm * 32 + mi * 16 + r + half * 8;
            int ge   = br + lrow;
            if (ge < E) {
                int s = s_src[lrow];
                int d = s_dst[lrow];
                const float* hp = hd  + (size_t)s * 128;
                float*       ap = agg + (size_t)d * 128;
#pragma unroll
                for (int ni = 0; ni < 8; ni++) {
                    int colb = wn * 64 + ni * 8 + 2 * c;
                    float2 hv = *(const float2*)(hp + colb);
                    float m0 = silu_f(acc[mi][ni][half * 2 + 0] + gb[colb])     * hv.x;
                    float m1 = silu_f(acc[mi][ni][half * 2 + 1] + gb[colb + 1]) * hv.y;
                    red2(ap + colb, m0, m1);
                }
            }
        }
    }
}

// ---------------------------------------------------------------------------
// Edge stage 1 (unchanged this round): t = silu([rel_pos|edge_attr]@[W1|W12]^T + b)
// ---------------------------------------------------------------------------
__global__ void __launch_bounds__(256, 2) edge_stage1(
    const float* __restrict__ rel_pos, const float* __restrict__ edge_attr,
    const float* __restrict__ w1, const float* __restrict__ b1,
    const float* __restrict__ w12, const float* __restrict__ b12,
    float* __restrict__ t, int E)
{
    __shared__ float As[8][128];
    __shared__ float Bs[8][128];

    const int tid = threadIdx.x;
    const int br  = blockIdx.x * 128;
    const int tr  = (tid >> 4) * 8;
    const int tc  = (tid & 15) * 8;
    const int lr  = tid & 127;
    const int kq  = (tid >> 7) * 4;

    float acc[8][8];
#pragma unroll
    for (int i = 0; i < 8; i++)
#pragma unroll
        for (int j = 0; j < 8; j++) acc[i][j] = 0.f;

    const int  ge   = br + lr;
    const bool e_ok = ge < E;

    for (int k0 = 0; k0 < 56; k0 += 8) {
#pragma unroll
        for (int q = 0; q < 4; q++) {
            int k = k0 + kq + q;
            float av = 0.f, wv = 0.f;
            if (e_ok) {
                if (k < 3)       av = rel_pos[(size_t)ge * 3 + k];
                else if (k < 53) av = edge_attr[(size_t)ge * 50 + (k - 3)];
            }
            if (lr < 64) {
                if (k < 3)       wv = w1[lr * 3 + k];
            } else {
                if (k >= 3 && k < 53) wv = w12[(lr - 64) * 50 + (k - 3)];
            }
            As[kq + q][lr] = av;
            Bs[kq + q][lr] = wv;
        }
        __syncthreads();
#pragma unroll
        for (int k = 0; k < 8; k++) {
            float4 a0 = *(const float4*)&As[k][tr];
            float4 a1 = *(const float4*)&As[k][tr + 4];
            float4 b0 = *(const float4*)&Bs[k][tc];
            float4 b1 = *(const float4*)&Bs[k][tc + 4];
            float a[8] = {a0.x, a0.y, a0.z, a0.w, a1.x, a1.y, a1.z, a1.w};
            float b[8] = {b0.x, b0.y, b0.z, b0.w, b1.x, b1.y, b1.z, b1.w};
#pragma unroll
            for (int i = 0; i < 8; i++)
#pragma unroll
                for (int j = 0; j < 8; j++)
                    acc[i][j] = fmaf(a[i], b[j], acc[i][j]);
        }
        __syncthreads();
    }

    float bb[8];
#pragma unroll
    for (int j = 0; j < 8; j++) {
        int cc = tc + j;
        bb[j] = (cc < 64) ? b1[cc] : b12[cc - 64];
    }

#pragma unroll
    for (int i = 0; i < 8; i++) {
        int g = br + tr + i;
        if (g < E) {
            float* row = t + (size_t)g * 128 + tc;
            float v[8];
#pragma unroll
            for (int j = 0; j < 8; j++) v[j] = silu_f(acc[i][j] + bb[j]);
            *(float4*)row       = make_float4(v[0], v[1], v[2], v[3]);
            *(float4*)(row + 4) = make_float4(v[4], v[5], v[6], v[7]);
        }
    }
}

// ---------------------------------------------------------------------------
__global__ void embed_concat(const int* __restrict__ z, const int* __restrict__ tag,
                             const float* __restrict__ emb_w,
                             const float* __restrict__ tag_emb_w,
                             float* __restrict__ h0, int N)
{
    int idx = blockIdx.x * blockDim.x + threadIdx.x;
    if (idx >= N * 64) return;
    int n = idx >> 6, c4 = idx & 63;
    float4 v;
    if (c4 < 56) v = ((const float4*)(emb_w + (size_t)z[n] * 224))[c4];
    else         v = ((const float4*)(tag_emb_w + (size_t)tag[n] * 32))[c4 - 56];
    ((float4*)(h0 + (size_t)n * 256))[c4] = v;
}

__global__ void stats_kernel(const float* __restrict__ agg, float* __restrict__ stats, int N)
{
    int col = threadIdx.x;
    float s = 0.f, s2 = 0.f;
    for (int r = blockIdx.x; r < N; r += gridDim.x) {
        float v = agg[(size_t)r * 128 + col];
        s += v;
        s2 = fmaf(v, v, s2);
    }
    atomicAdd(&stats[col], s);
    atomicAdd(&stats[128 + col], s2);
}

__global__ void finalize_stats(float* stats, const float* __restrict__ gnw,
                               const float* __restrict__ gnms, int N)
{
    int f = threadIdx.x;
    float inv  = 1.f / (float)N;
    float mean = stats[f] * inv;
    float m2   = stats[128 + f] * inv;
    float ms   = gnms[f];
    float var = m2 - ms * (2.f - ms) * mean * mean;
    stats[256 + f] = mean * ms;
    stats[384 + f] = gnw[f] * rsqrtf(var + 1e-5f);
}

__global__ void apply_gn(const float* __restrict__ agg, const float* __restrict__ stats,
                         const float* __restrict__ gnb, float* __restrict__ x, int total4)
{
    int i = blockIdx.x * blockDim.x + threadIdx.x;
    if (i >= total4) return;
    int f = (i & 31) * 4;
    float4 v = ((const float4*)agg)[i];
    float4 o;
    o.x = silu_f(stats[384 + f + 0] * (v.x - stats[256 + f + 0]) + gnb[f + 0]);
    o.y = silu_f(stats[384 + f + 1] * (v.y - stats[256 + f + 1]) + gnb[f + 1]);
    o.z = silu_f(stats[384 + f + 2] * (v.z - stats[256 + f + 2]) + gnb[f + 2]);
    o.w = silu_f(stats[384 + f + 3] * (v.w - stats[256 + f + 3]) + gnb[f + 3]);
    ((float4*)x)[i] = o;
}

__global__ void out_reduce(const float* __restrict__ h1, const float* __restrict__ w2,
                           const float* __restrict__ b2, const int* __restrict__ batch,
                           float* __restrict__ out, int N)
{
    int gw   = (blockIdx.x * blockDim.x + threadIdx.x) >> 5;
    int lane = threadIdx.x & 31;
    if (gw >= N) return;
    float4 a = ((const float4*)(h1 + (size_t)gw * 128))[lane];
    float4 b = ((const float4*)w2)[lane];
    float s = a.x * b.x + a.y * b.y + a.z * b.z + a.w * b.w;
#pragma unroll
    for (int o = 16; o > 0; o >>= 1) s += __shfl_xor_sync(0xffffffffu, s, o);
    if (lane == 0) atomicAdd(&out[batch[gw]], s + b2[0]);
}

__global__ void zero_kernel(float* __restrict__ p, int n4)
{
    int i = blockIdx.x * blockDim.x + threadIdx.x;
    if (i < n4) ((float4*)p)[i] = make_float4(0.f, 0.f, 0.f, 0.f);
}

// ---------------------------------------------------------------------------
extern "C" void kernel_launch(void* const* d_in, const int* in_sizes, int n_in,
                              void* d_out, int out_size)
{
    const int*   z         = (const int*)  d_in[0];
    const int*   tag       = (const int*)  d_in[1];
    const float* rel_pos   = (const float*)d_in[2];
    const float* edge_attr = (const float*)d_in[3];
    const int*   ei        = (const int*)  d_in[4];
    const int*   batch     = (const int*)  d_in[5];
    const float* lin_e1_w  = (const float*)d_in[6];
    const float* lin_e1_b  = (const float*)d_in[7];
    const float* lin_e12_w = (const float*)d_in[8];
    const float* lin_e12_b = (const float*)d_in[9];
    const float* lin_e2_w  = (const float*)d_in[10];
    const float* lin_e2_b  = (const float*)d_in[11];
    const float* emb_w     = (const float*)d_in[12];
    const float* tag_emb_w = (const float*)d_in[13];
    const float* lin_w     = (const float*)d_in[14];
    const float* lin_b     = (const float*)d_in[15];
    const float* lin2_w    = (const float*)d_in[16];
    const float* lin2_b    = (const float*)d_in[17];
    const float* geom_w    = (const float*)d_in[18];
    const float* geom_b    = (const float*)d_in[19];
    const float* down_w    = (const float*)d_in[20];
    const float* down_b    = (const float*)d_in[21];
    const float* up_w      = (const float*)d_in[22];
    const float* up_b      = (const float*)d_in[23];
    const float* gn_w      = (const float*)d_in[24];
    const float* gn_b      = (const float*)d_in[25];
    const float* gn_ms     = (const float*)d_in[26];
    const float* out1_w    = (const float*)d_in[27];
    const float* out1_b    = (const float*)d_in[28];
    const float* out2_w    = (const float*)d_in[29];
    const float* out2_b    = (const float*)d_in[30];
    float*       out       = (float*)d_out;

    const int N = in_sizes[0];
    const int E = in_sizes[2] / 3;

    float *h0, *hb, *h, *hd, *agg, *stats, *t, *e;
    cudaGetSymbolAddress((void**)&h0,    g_h0);
    cudaGetSymbolAddress((void**)&hb,    g_hb);
    cudaGetSymbolAddress((void**)&h,     g_h);
    cudaGetSymbolAddress((void**)&hd,    g_hd);
    cudaGetSymbolAddress((void**)&agg,   g_agg);
    cudaGetSymbolAddress((void**)&stats, g_stats);
    cudaGetSymbolAddress((void**)&t,     g_t);
    cudaGetSymbolAddress((void**)&e,     g_e);

    const int mbn = (N + 127) / 128;
    const int mbe = (E + 127) / 128;

    // Node embedding
    embed_concat<<<(N * 64 + 255) / 256, 256>>>(z, tag, emb_w, tag_emb_w, h0, N);
    gemm_tc<<<dim3(mbn, 2), 256>>>(h0, lin_w,  lin_b,  hb, nullptr, N, 256, 256);
    gemm_tc<<<dim3(mbn, 2), 256>>>(hb, lin2_w, lin2_b, h,  nullptr, N, 256, 256);

    // Edge embedding
    edge_stage1<<<mbe, 256>>>(rel_pos, edge_attr, lin_e1_w, lin_e1_b,
                              lin_e12_w, lin_e12_b, t, E);
    gemm_tc<<<dim3(mbe, 1), 256>>>(t, lin_e2_w, lin_e2_b, e, nullptr, E, 128, 128);

    // Interaction layers
    for (int l = 0; l < 3; l++) {
        gemm_tc<<<dim3(mbn, 1), 256>>>(h, down_w + (size_t)l * 128 * 256,
                                       down_b + l * 128, hd, nullptr, N, 128, 256);
        zero_kernel<<<(N * 32 + 255) / 256, 256>>>(agg, N * 32);
        zero_kernel<<<1, 64>>>(stats, 64);
        message_tc<<<mbe, 256>>>(e, geom_w + (size_t)l * 128 * 128,
                                 geom_b + l * 128, hd, ei, agg, E);
        stats_kernel<<<256, 128>>>(agg, stats, N);
        finalize_stats<<<1, 128>>>(stats, gn_w + l * 128, gn_ms + l * 128, N);
        apply_gn<<<(N * 32 + 255) / 256, 256>>>(agg, stats, gn_b + l * 128, hd, N * 32);
        gemm_tc<<<dim3(mbn, 2), 256>>>(hd, up_w + (size_t)l * 256 * 128,
                                       up_b + l * 256, h, h, N, 256, 128);
    }

    // Output block
    gemm_tc<<<dim3(mbn, 1), 256>>>(h, out1_w, out1_b, hd, nullptr, N, 128, 256);
    zero_kernel<<<1, 8>>>(out, 8);
    out_reduce<<<(N * 32 + 255) / 256, 256>>>(hd, out2_w, out2_b, batch, out, N);
}